// round 1
// baseline (speedup 1.0000x reference)
#include <cuda_runtime.h>
#include <math.h>

#define BB 256
#define MAXLEN 31
#define TT 30
#define VV 10000
#define HH 512
#define EE 512
#define G4 2048   // 4*H
#define KX 512    // K dim of all GEMMs

// ---------------- scratch (static device globals; zero-initialized at load) ----
__device__ int   d_order[BB];
__device__ int   d_cnt[MAXLEN];                 // cnt[t] = #batches with dec_len > t
__device__ float d_hstate[BB * HH];
__device__ float d_cstate[BB * HH];
__device__ float d_Gpart[BB * G4];              // image part of gates + biases
__device__ float d_Z[(size_t)TT * BB * G4];     // full x-part pre-gates, row r = t*256+b
__device__ float d_gates[BB * G4];              // per-step gate scratch
__device__ float d_Hnew[(size_t)TT * BB * HH];  // h_new per step (input to projection)

// ---------------- zero h/c state each launch (graph replays must reset) -------
__global__ void k_zero() {
    int i = blockIdx.x * 256 + threadIdx.x;
    d_hstate[i] = 0.f;
    d_cstate[i] = 0.f;
}

// ---------------- sort (stable descending), target + dec_len outputs, cnt[] ---
__global__ void k_sort(const int* __restrict__ caplen,
                       const int* __restrict__ w_input,
                       float* __restrict__ out, long long out_elems) {
    __shared__ int sl[BB];
    __shared__ int sdecl[BB];
    __shared__ int sord[BB];
    int tid = threadIdx.x;
    int len = caplen[tid];
    sl[tid] = len;
    __syncthreads();
    int rank = 0;
    for (int j = 0; j < BB; j++) {
        int lj = sl[j];
        rank += (lj > len) || (lj == len && j < tid);   // stable ties by index
    }
    sord[rank] = tid;
    sdecl[rank] = len - 1;
    d_order[rank] = tid;
    __syncthreads();

    const long long PRED = (long long)BB * MAXLEN * VV;
    if (out_elems >= PRED + BB * TT + BB)
        out[PRED + BB * TT + rank] = (float)(len - 1);
    // target = sorted w[:, 1:]
    if (out_elems >= PRED + BB * TT) {
        int src = sord[tid];
        for (int t = 0; t < TT; t++)
            out[PRED + (long long)tid * TT + t] = (float)w_input[src * MAXLEN + t + 1];
    }
    if (tid < MAXLEN) {
        int c = 0;
        for (int b = 0; b < BB; b++) c += (sdecl[b] > tid);
        d_cnt[tid] = c;
    }
}

// ---------------- common GEMM tile: 64x64, K=512, KT=32, 256 thr, 4x4 micro ---
// As/Bs stored [k][m]/[k][n], pitch 68 (16B-aligned rows).

// Gpart: C[b][j] = g_sorted[b] . W_ih[j][0:512] + b_ih[j] + b_hh[j]
__global__ __launch_bounds__(256) void k_gpart(const float* __restrict__ gimg,
                                               const float* __restrict__ W_ih,
                                               const float* __restrict__ b_ih,
                                               const float* __restrict__ b_hh) {
    __shared__ float As[32][68];
    __shared__ float Bs[32][68];
    __shared__ int rows[64];
    const int m0 = blockIdx.y * 64, n0 = blockIdx.x * 64;
    if (threadIdx.x < 64) rows[threadIdx.x] = d_order[m0 + threadIdx.x];
    __syncthreads();
    float acc[4][4] = {};
    const int tx = threadIdx.x & 15, ty = threadIdx.x >> 4;
    for (int k0 = 0; k0 < KX; k0 += 32) {
#pragma unroll
        for (int i = 0; i < 2; i++) {
            int vec = threadIdx.x * 2 + i;
            int m = vec >> 3, kv = (vec & 7) << 2;
            float4 va = *(const float4*)&gimg[(size_t)rows[m] * EE + k0 + kv];
            As[kv + 0][m] = va.x; As[kv + 1][m] = va.y; As[kv + 2][m] = va.z; As[kv + 3][m] = va.w;
            float4 vb = *(const float4*)&W_ih[(size_t)(n0 + m) * 1024 + k0 + kv];
            Bs[kv + 0][m] = vb.x; Bs[kv + 1][m] = vb.y; Bs[kv + 2][m] = vb.z; Bs[kv + 3][m] = vb.w;
        }
        __syncthreads();
#pragma unroll
        for (int kk = 0; kk < 32; kk++) {
            float4 a = *(const float4*)&As[kk][ty << 2];
            float4 b = *(const float4*)&Bs[kk][tx << 2];
            float av[4] = {a.x, a.y, a.z, a.w};
            float bv[4] = {b.x, b.y, b.z, b.w};
#pragma unroll
            for (int i2 = 0; i2 < 4; i2++)
#pragma unroll
                for (int j2 = 0; j2 < 4; j2++) acc[i2][j2] += av[i2] * bv[j2];
        }
        __syncthreads();
    }
#pragma unroll
    for (int i2 = 0; i2 < 4; i2++) {
        int m = m0 + (ty << 2) + i2;
#pragma unroll
        for (int j2 = 0; j2 < 4; j2++) {
            int n = n0 + (tx << 2) + j2;
            d_Gpart[m * G4 + n] = acc[i2][j2] + b_ih[n] + b_hh[n];
        }
    }
}

// Epart: Z[r][j] = emb[tok(r)] . W_ih[j][512:1024] + Gpart[b][j],  r = t*256+b
__global__ __launch_bounds__(256) void k_epart(const float* __restrict__ emb,
                                               const float* __restrict__ W_ih,
                                               const int* __restrict__ w_input) {
    const int m0 = blockIdx.y * 64, n0 = blockIdx.x * 64;
    const int t = m0 >> 8, b0 = m0 & 255;
    if (b0 >= d_cnt[t]) return;   // whole tile inactive -> skip (Z stays 0)
    __shared__ float As[32][68];
    __shared__ float Bs[32][68];
    __shared__ int toks[64];
    if (threadIdx.x < 64)
        toks[threadIdx.x] = w_input[d_order[b0 + threadIdx.x] * MAXLEN + t];
    __syncthreads();
    float acc[4][4] = {};
    const int tx = threadIdx.x & 15, ty = threadIdx.x >> 4;
    for (int k0 = 0; k0 < KX; k0 += 32) {
#pragma unroll
        for (int i = 0; i < 2; i++) {
            int vec = threadIdx.x * 2 + i;
            int m = vec >> 3, kv = (vec & 7) << 2;
            float4 va = *(const float4*)&emb[(size_t)toks[m] * EE + k0 + kv];
            As[kv + 0][m] = va.x; As[kv + 1][m] = va.y; As[kv + 2][m] = va.z; As[kv + 3][m] = va.w;
            float4 vb = *(const float4*)&W_ih[(size_t)(n0 + m) * 1024 + 512 + k0 + kv];
            Bs[kv + 0][m] = vb.x; Bs[kv + 1][m] = vb.y; Bs[kv + 2][m] = vb.z; Bs[kv + 3][m] = vb.w;
        }
        __syncthreads();
#pragma unroll
        for (int kk = 0; kk < 32; kk++) {
            float4 a = *(const float4*)&As[kk][ty << 2];
            float4 b = *(const float4*)&Bs[kk][tx << 2];
            float av[4] = {a.x, a.y, a.z, a.w};
            float bv[4] = {b.x, b.y, b.z, b.w};
#pragma unroll
            for (int i2 = 0; i2 < 4; i2++)
#pragma unroll
                for (int j2 = 0; j2 < 4; j2++) acc[i2][j2] += av[i2] * bv[j2];
        }
        __syncthreads();
    }
#pragma unroll
    for (int i2 = 0; i2 < 4; i2++) {
        int lm = (ty << 2) + i2;
        int r = m0 + lm, b = b0 + lm;
#pragma unroll
        for (int j2 = 0; j2 < 4; j2++) {
            int n = n0 + (tx << 2) + j2;
            d_Z[(size_t)r * G4 + n] = acc[i2][j2] + d_Gpart[b * G4 + n];
        }
    }
}

// Step GEMM: gates[b][j] = h_state[b] . W_hh[j] + Z[t*256+b][j]
__global__ __launch_bounds__(256) void k_step(const float* __restrict__ W_hh, int t) {
    const int m0 = blockIdx.y * 64, n0 = blockIdx.x * 64;
    if (m0 >= d_cnt[t]) return;
    __shared__ float As[32][68];
    __shared__ float Bs[32][68];
    float acc[4][4] = {};
    const int tx = threadIdx.x & 15, ty = threadIdx.x >> 4;
    for (int k0 = 0; k0 < KX; k0 += 32) {
#pragma unroll
        for (int i = 0; i < 2; i++) {
            int vec = threadIdx.x * 2 + i;
            int m = vec >> 3, kv = (vec & 7) << 2;
            float4 va = *(const float4*)&d_hstate[(size_t)(m0 + m) * HH + k0 + kv];
            As[kv + 0][m] = va.x; As[kv + 1][m] = va.y; As[kv + 2][m] = va.z; As[kv + 3][m] = va.w;
            float4 vb = *(const float4*)&W_hh[(size_t)(n0 + m) * HH + k0 + kv];
            Bs[kv + 0][m] = vb.x; Bs[kv + 1][m] = vb.y; Bs[kv + 2][m] = vb.z; Bs[kv + 3][m] = vb.w;
        }
        __syncthreads();
#pragma unroll
        for (int kk = 0; kk < 32; kk++) {
            float4 a = *(const float4*)&As[kk][ty << 2];
            float4 b = *(const float4*)&Bs[kk][tx << 2];
            float av[4] = {a.x, a.y, a.z, a.w};
            float bv[4] = {b.x, b.y, b.z, b.w};
#pragma unroll
            for (int i2 = 0; i2 < 4; i2++)
#pragma unroll
                for (int j2 = 0; j2 < 4; j2++) acc[i2][j2] += av[i2] * bv[j2];
        }
        __syncthreads();
    }
#pragma unroll
    for (int i2 = 0; i2 < 4; i2++) {
        int m = m0 + (ty << 2) + i2;
#pragma unroll
        for (int j2 = 0; j2 < 4; j2++) {
            int n = n0 + (tx << 2) + j2;
            d_gates[m * G4 + n] = acc[i2][j2] + d_Z[((size_t)t * BB + m) * G4 + n];
        }
    }
}

// LSTM cell pointwise; only active rows update state / write Hnew
__global__ void k_cell(int t) {
    int idx = blockIdx.x * 256 + threadIdx.x;   // 0..131071
    int b = idx >> 9;
    if (b >= d_cnt[t]) return;
    int h = idx & 511;
    const float* gr = d_gates + b * G4;
    float vi = gr[h], vf = gr[512 + h], vg = gr[1024 + h], vo = gr[1536 + h];
    float ii = 1.f / (1.f + expf(-vi));
    float ff = 1.f / (1.f + expf(-vf));
    float oo = 1.f / (1.f + expf(-vo));
    float gg = tanhf(vg);
    float c = ff * d_cstate[idx] + ii * gg;
    float hn = oo * tanhf(c);
    d_cstate[idx] = c;
    d_hstate[idx] = hn;
    d_Hnew[(size_t)t * (BB * HH) + idx] = hn;
}

// Projection: out[(b*31+t)*V + v] = Hnew[t*256+b] . W_out[v] + b_out[v]
__global__ __launch_bounds__(256) void k_proj(const float* __restrict__ W_out,
                                              const float* __restrict__ b_out,
                                              float* __restrict__ out) {
    const int m0 = blockIdx.y * 64, n0 = blockIdx.x * 64;
    const int t = m0 >> 8, b0 = m0 & 255;
    if (b0 >= d_cnt[t]) return;
    __shared__ float As[32][68];
    __shared__ float Bs[32][68];
    float acc[4][4] = {};
    const int tx = threadIdx.x & 15, ty = threadIdx.x >> 4;
    for (int k0 = 0; k0 < KX; k0 += 32) {
#pragma unroll
        for (int i = 0; i < 2; i++) {
            int vec = threadIdx.x * 2 + i;
            int m = vec >> 3, kv = (vec & 7) << 2;
            float4 va = *(const float4*)&d_Hnew[(size_t)(m0 + m) * HH + k0 + kv];
            As[kv + 0][m] = va.x; As[kv + 1][m] = va.y; As[kv + 2][m] = va.z; As[kv + 3][m] = va.w;
            int v = n0 + m;
            float4 vb = make_float4(0.f, 0.f, 0.f, 0.f);
            if (v < VV) vb = *(const float4*)&W_out[(size_t)v * HH + k0 + kv];
            Bs[kv + 0][m] = vb.x; Bs[kv + 1][m] = vb.y; Bs[kv + 2][m] = vb.z; Bs[kv + 3][m] = vb.w;
        }
        __syncthreads();
#pragma unroll
        for (int kk = 0; kk < 32; kk++) {
            float4 a = *(const float4*)&As[kk][ty << 2];
            float4 b = *(const float4*)&Bs[kk][tx << 2];
            float av[4] = {a.x, a.y, a.z, a.w};
            float bv[4] = {b.x, b.y, b.z, b.w};
#pragma unroll
            for (int i2 = 0; i2 < 4; i2++)
#pragma unroll
                for (int j2 = 0; j2 < 4; j2++) acc[i2][j2] += av[i2] * bv[j2];
        }
        __syncthreads();
    }
#pragma unroll
    for (int i2 = 0; i2 < 4; i2++) {
        int lm = (ty << 2) + i2;
        int b = b0 + lm;
#pragma unroll
        for (int j2 = 0; j2 < 4; j2++) {
            int n = n0 + (tx << 2) + j2;
            if (n < VV)
                out[((size_t)b * MAXLEN + t) * VV + n] = acc[i2][j2] + b_out[n];
        }
    }
}

// log_softmax in place; inactive rows (t==30 or b>=cnt[t]) -> zeros
__global__ __launch_bounds__(256) void k_lsm(float* __restrict__ out) {
    __shared__ float sx[VV];
    __shared__ float red[256];
    int rid = blockIdx.x;
    int b = rid / MAXLEN, t = rid - b * MAXLEN;
    float* row = out + (size_t)rid * VV;
    int tid = threadIdx.x;
    bool active = (t < TT) && (b < d_cnt[t]);
    if (!active) {
        for (int i = tid; i < VV; i += 256) row[i] = 0.f;
        return;
    }
    float mx = -1e30f;
    for (int i = tid; i < VV; i += 256) {
        float v = row[i];
        sx[i] = v;
        mx = fmaxf(mx, v);
    }
    red[tid] = mx;
    __syncthreads();
    for (int s = 128; s > 0; s >>= 1) {
        if (tid < s) red[tid] = fmaxf(red[tid], red[tid + s]);
        __syncthreads();
    }
    mx = red[0];
    __syncthreads();
    float sm = 0.f;
    for (int i = tid; i < VV; i += 256) sm += expf(sx[i] - mx);
    red[tid] = sm;
    __syncthreads();
    for (int s = 128; s > 0; s >>= 1) {
        if (tid < s) red[tid] += red[tid + s];
        __syncthreads();
    }
    float lse = mx + logf(red[0]);
    for (int i = tid; i < VV; i += 256) row[i] = sx[i] - lse;
}

// ---------------- launch ------------------------------------------------------
extern "C" void kernel_launch(void* const* d_in, const int* in_sizes, int n_in,
                              void* d_out, int out_size) {
    const float* gimg    = (const float*)d_in[0];
    const int*   w_input = (const int*)  d_in[1];
    const int*   caplen  = (const int*)  d_in[2];
    const float* emb     = (const float*)d_in[3];
    const float* W_ih    = (const float*)d_in[4];
    const float* W_hh    = (const float*)d_in[5];
    const float* b_ih    = (const float*)d_in[6];
    const float* b_hh    = (const float*)d_in[7];
    const float* W_out   = (const float*)d_in[8];
    const float* b_out   = (const float*)d_in[9];
    float* out = (float*)d_out;

    k_zero<<<512, 256>>>();
    k_sort<<<1, 256>>>(caplen, w_input, out, (long long)out_size);
    k_gpart<<<dim3(32, 4), 256>>>(gimg, W_ih, b_ih, b_hh);
    k_epart<<<dim3(32, 120), 256>>>(emb, W_ih, w_input);
    for (int t = 0; t < TT; t++) {
        k_step<<<dim3(32, 4), 256>>>(W_hh, t);
        k_cell<<<512, 256>>>(t);
    }
    k_proj<<<dim3(157, 120), 256>>>(W_out, b_out, out);
    k_lsm<<<BB * MAXLEN, 256>>>(out);
}